// round 17
// baseline (speedup 1.0000x reference)
#include <cuda_runtime.h>
#include <cuda_bf16.h>
#include <cstdint>
#include <cstddef>

// Problem constants
#define BB   8
#define CC   512
#define TT_  4096
#define HH   4
#define KK   16
#define VV   128
#define RR   15
#define NCH  208          // 64 q + 16 k + 128 v
#define NQ   64
#define NV   128
#define MPAD 256
#define NT   32768        // BB*TT_
#define PSTG 16           // paired stages: 8x (xh: Wh+Wl) + 8x (xl: Wh)

// ---------------- scratch ----------------
__device__ float g_proj[(size_t)BB * NCH * TT_];        // [8][208][4096]
__device__ float g_scale[192];
__device__ float g_shift[192];
__device__ float g_part[(size_t)BB * 32 * KK * VV];
__device__ float g_lambda[(size_t)BB * KK * VV];
__device__ float g_bnp[192 * 8 * 2];
__device__ float g_kstat[BB * KK * 2];                  // per (b,k): max, 1/sumexp
__device__ __nv_bfloat16 g_Wh[MPAD * CC];
__device__ __nv_bfloat16 g_Wl[MPAD * CC];
__device__ __nv_bfloat16 g_xh[(size_t)NT * CC];         // [b*t][c]
__device__ __nv_bfloat16 g_xl[(size_t)NT * CC];

// ---------------- helpers ----------------
__device__ __forceinline__ uint32_t smem_u32(const void* p) {
    uint32_t a;
    asm("{ .reg .u64 t; cvta.to.shared.u64 t, %1; cvt.u32.u64 %0, t; }" : "=r"(a) : "l"(p));
    return a;
}
#define SWZ128(off) ((off) ^ (((off) >> 3) & 0x70))
#define CP_ASYNC16(dst, src) \
    asm volatile("cp.async.cg.shared.global [%0], [%1], 16;" :: "r"(dst), "l"(src))

__device__ __forceinline__ void ldsm_x4(uint32_t& r0, uint32_t& r1, uint32_t& r2, uint32_t& r3,
                                        uint32_t addr) {
    asm volatile("ldmatrix.sync.aligned.m8n8.x4.shared.b16 {%0,%1,%2,%3}, [%4];"
        : "=r"(r0), "=r"(r1), "=r"(r2), "=r"(r3) : "r"(addr));
}
#define MMA16816(c, a, b0, b1) \
    asm volatile("mma.sync.aligned.m16n8k16.row.col.f32.bf16.bf16.f32 " \
        "{%0,%1,%2,%3}, {%4,%5,%6,%7}, {%8,%9}, {%0,%1,%2,%3};" \
        : "+f"((c)[0]), "+f"((c)[1]), "+f"((c)[2]), "+f"((c)[3]) \
        : "r"((a)[0]), "r"((a)[1]), "r"((a)[2]), "r"((a)[3]), "r"(b0), "r"(b1))

// ---------------- pack W, split into bf16 hi/lo (padded to 256 rows) ----------------
__global__ void pack_w_split(const float* __restrict__ Wq, const float* __restrict__ Wk,
                             const float* __restrict__ Wv) {
    int i = blockIdx.x * 256 + threadIdx.x;
    if (i >= MPAD * CC) return;
    int ch = i / CC, c = i % CC;
    float w = 0.f;
    if (ch < 64)       w = Wq[ch * CC + c];
    else if (ch < 80)  w = Wk[(ch - 64) * CC + c];
    else if (ch < NCH) w = Wv[(ch - 80) * CC + c];
    __nv_bfloat16 h = __float2bfloat16(w);
    g_Wh[i] = h;
    g_Wl[i] = __float2bfloat16(w - __bfloat162float(h));
}

// ---------------- transpose + split x v4: conflict-free XOR-swizzled smem ----------------
// tile 64(t) x 64(c); smem s[c][68]; float4 stored at t-quad (q ^ (c>>3)).
__global__ __launch_bounds__(256) void xsplit(const float* __restrict__ x) {
    __shared__ float s[64][68];
    const int b = blockIdx.z, c0 = blockIdx.y * 64, t0 = blockIdx.x * 64;
    const int tid = threadIdx.x;
    const float* xp = x + ((size_t)b * CC + c0) * TT_ + t0;

    // load: thread -> (c-row r, t-quad q); store swizzled float4
#pragma unroll
    for (int i = 0; i < 4; i++) {
        const int idx = tid + i * 256;
        const int r = idx >> 4, q = idx & 15;
        const float4 v = *(const float4*)(xp + (size_t)r * TT_ + q * 4);
        *(float4*)&s[r][((q ^ (r >> 3)) & 15) * 4] = v;
    }
    __syncthreads();

    // write: thread -> (t-row tr, c-octet cw); gather 8 c values, pack, 1 STG.128 per array
    const size_t row0 = (size_t)b * TT_ + t0;
#pragma unroll
    for (int i = 0; i < 2; i++) {
        const int task = tid + i * 256;
        const int tr = task >> 3, cw = task & 7;
        float f[8];
#pragma unroll
        for (int j = 0; j < 8; j++) {
            const int rr = cw * 8 + j;
            f[j] = s[rr][(((tr >> 2) ^ cw) & 15) * 4 + (tr & 3)];
        }
        uint32_t hw[4], lw[4];
#pragma unroll
        for (int j = 0; j < 4; j++) {
            const float a = f[2 * j], bb2 = f[2 * j + 1];
            __nv_bfloat162 h2 = make_bfloat162(__float2bfloat16(a), __float2bfloat16(bb2));
            __nv_bfloat162 l2 = make_bfloat162(__float2bfloat16(a - __bfloat162float(h2.x)),
                                               __float2bfloat16(bb2 - __bfloat162float(h2.y)));
            hw[j] = *(uint32_t*)&h2;
            lw[j] = *(uint32_t*)&l2;
        }
        const size_t base = (row0 + tr) * CC + c0 + cw * 8;
        *(uint4*)(g_xh + base) = make_uint4(hw[0], hw[1], hw[2], hw[3]);
        *(uint4*)(g_xl + base) = make_uint4(lw[0], lw[1], lw[2], lw[3]);
    }
}

// ---------------- mma.sync bf16 projection GEMM ----------------
// D[ch][gt] = Wh.xh + Wl.xh + Wh.xl
// CTA 128(m) x 128(n), 128 threads (4 warps, 2M x 2N), warp 64x64.
// Stage = A0 16KB | A1 16KB | B 16KB = 48KB, double-buffered (96KB) -> 2 CTAs/SM.
#define STG_BYTES 49152
#define GM_SMEM (2 * STG_BYTES)

__global__ __launch_bounds__(128, 2) void gemm_mma() {
    extern __shared__ __align__(128) char smem[];
    const uint32_t sb = smem_u32(smem);
    const int tid = threadIdx.x;
    const int wid = tid >> 5, lane = tid & 31;
    const int n0 = blockIdx.x * 128;       // flattened b*t column base
    const int m0 = blockIdx.y * 128;       // channel base
    const int wm = wid & 1, wn = wid >> 1; // warp tile origin (m:2, n:2)
    const int ml = lane >> 3, rin = lane & 7;

    float acc[4][8][4];
#pragma unroll
    for (int i = 0; i < 4; i++)
#pragma unroll
        for (int j = 0; j < 8; j++)
#pragma unroll
            for (int k = 0; k < 4; k++) acc[i][j][k] = 0.f;

    auto issue = [&](int p) {
        const bool dual = p < 8;
        const int koff = (p & 7) * 64;
        const __nv_bfloat16* bseg = dual ? g_xh : g_xl;
        const uint32_t st = sb + (p & 1) * STG_BYTES;
#pragma unroll
        for (int j = 0; j < 8; j++) {
            int idx = tid + j * 128;
            int r = idx >> 3, cc = idx & 7;
            const uint32_t dsw = SWZ128((uint32_t)(r * 128 + cc * 16));
            CP_ASYNC16(st + dsw, g_Wh + (size_t)(m0 + r) * CC + koff + cc * 8);
            if (dual)
                CP_ASYNC16(st + 16384 + dsw, g_Wl + (size_t)(m0 + r) * CC + koff + cc * 8);
            CP_ASYNC16(st + 32768 + dsw, bseg + (size_t)(n0 + r) * CC + koff + cc * 8);
        }
        asm volatile("cp.async.commit_group;");
    };

    auto compute_pair = [&](uint32_t stA0, uint32_t stA1, uint32_t stB, bool dual) {
#pragma unroll
        for (int ks = 0; ks < 4; ks++) {
            uint32_t bfr[4][4];
#pragma unroll
            for (int bi = 0; bi < 4; bi++) {
                const int n = wn * 64 + bi * 16 + (ml >> 1) * 8 + rin;
                const int kc = 2 * ks + (ml & 1);
                ldsm_x4(bfr[bi][0], bfr[bi][1], bfr[bi][2], bfr[bi][3],
                        stB + n * 128 + ((kc ^ (n & 7)) << 4));
            }
            uint32_t a[4][4];
#pragma unroll
            for (int mi = 0; mi < 4; mi++) {
                const int row = wm * 64 + mi * 16 + (ml & 1) * 8 + rin;
                const int kc = 2 * ks + (ml >> 1);
                ldsm_x4(a[mi][0], a[mi][1], a[mi][2], a[mi][3],
                        stA0 + row * 128 + ((kc ^ (row & 7)) << 4));
            }
#pragma unroll
            for (int mi = 0; mi < 4; mi++)
#pragma unroll
                for (int ni = 0; ni < 8; ni++)
                    MMA16816(acc[mi][ni], a[mi],
                             bfr[ni >> 1][(ni & 1) * 2], bfr[ni >> 1][(ni & 1) * 2 + 1]);
            if (dual) {
#pragma unroll
                for (int mi = 0; mi < 4; mi++) {
                    const int row = wm * 64 + mi * 16 + (ml & 1) * 8 + rin;
                    const int kc = 2 * ks + (ml >> 1);
                    ldsm_x4(a[mi][0], a[mi][1], a[mi][2], a[mi][3],
                            stA1 + row * 128 + ((kc ^ (row & 7)) << 4));
                }
#pragma unroll
                for (int mi = 0; mi < 4; mi++)
#pragma unroll
                    for (int ni = 0; ni < 8; ni++)
                        MMA16816(acc[mi][ni], a[mi],
                                 bfr[ni >> 1][(ni & 1) * 2], bfr[ni >> 1][(ni & 1) * 2 + 1]);
            }
        }
    };

    issue(0);
#pragma unroll 1
    for (int p = 0; p < PSTG; p++) {
        if (p + 1 < PSTG) {
            issue(p + 1);
            asm volatile("cp.async.wait_group 1;");
        } else {
            asm volatile("cp.async.wait_group 0;");
        }
        __syncthreads();
        const uint32_t st = sb + (p & 1) * STG_BYTES;
        compute_pair(st, st + 16384, st + 32768, p < 8);
        __syncthreads();
    }

    // epilogue
    const int b = n0 >> 12;
    const int t0 = n0 & (TT_ - 1);
#pragma unroll
    for (int mi = 0; mi < 4; mi++) {
#pragma unroll
        for (int h = 0; h < 2; h++) {
            const int ch = m0 + wm * 64 + mi * 16 + (lane >> 2) + h * 8;
            if (ch < NCH) {
                float* p = g_proj + ((size_t)b * NCH + ch) * TT_ + t0 + wn * 64 + (lane & 3) * 2;
#pragma unroll
                for (int ni = 0; ni < 8; ni++) {
                    float2 v = make_float2(acc[mi][ni][h * 2], acc[mi][ni][h * 2 + 1]);
                    *(float2*)(p + ni * 8) = v;
                }
            }
        }
    }
}

// ---------------- merged stats: BN partials (ci<192) + k softmax stats (ci>=192) ----------------
__global__ __launch_bounds__(256) void stats_part() {
    const int ci = blockIdx.x, bb = blockIdx.y;
    const int tid = threadIdx.x;
    if (ci < 192) {
        const int ch = ci < 64 ? ci : ci + 16;
        const float* p = g_proj + ((size_t)bb * NCH + ch) * TT_;
        float s = 0.f, s2 = 0.f;
        for (int i = tid * 4; i < TT_; i += 256 * 4) {
            float4 v = *(const float4*)(p + i);
            s += v.x + v.y + v.z + v.w;
            s2 += v.x * v.x + v.y * v.y + v.z * v.z + v.w * v.w;
        }
#pragma unroll
        for (int o = 16; o > 0; o >>= 1) {
            s  += __shfl_down_sync(0xffffffffu, s, o);
            s2 += __shfl_down_sync(0xffffffffu, s2, o);
        }
        __shared__ float ws[8], ws2[8];
        if ((tid & 31) == 0) { ws[tid >> 5] = s; ws2[tid >> 5] = s2; }
        __syncthreads();
        if (tid == 0) {
            float t = 0.f, t2 = 0.f;
#pragma unroll
            for (int w = 0; w < 8; w++) { t += ws[w]; t2 += ws2[w]; }
            g_bnp[(ci * 8 + bb) * 2]     = t;
            g_bnp[(ci * 8 + bb) * 2 + 1] = t2;
        }
    } else {
        const int k = ci - 192;
        const float* row = g_proj + ((size_t)bb * NCH + 64 + k) * TT_;
        float m = -1e30f;
        for (int i = tid * 4; i < TT_; i += 1024) {
            float4 v = *(const float4*)(row + i);
            m = fmaxf(m, fmaxf(fmaxf(v.x, v.y), fmaxf(v.z, v.w)));
        }
#pragma unroll
        for (int o = 16; o > 0; o >>= 1) m = fmaxf(m, __shfl_xor_sync(0xffffffffu, m, o));
        __shared__ float wm[8];
        if ((tid & 31) == 0) wm[tid >> 5] = m;
        __syncthreads();
        m = fmaxf(fmaxf(fmaxf(wm[0], wm[1]), fmaxf(wm[2], wm[3])),
                  fmaxf(fmaxf(wm[4], wm[5]), fmaxf(wm[6], wm[7])));
        float s = 0.f;
        for (int i = tid * 4; i < TT_; i += 1024) {
            float4 v = *(const float4*)(row + i);
            s += expf(v.x - m) + expf(v.y - m) + expf(v.z - m) + expf(v.w - m);
        }
#pragma unroll
        for (int o = 16; o > 0; o >>= 1) s += __shfl_xor_sync(0xffffffffu, s, o);
        __shared__ float wsum[8];
        if ((tid & 31) == 0) wsum[tid >> 5] = s;
        __syncthreads();
        if (tid == 0) {
            float t = 0.f;
#pragma unroll
            for (int w = 0; w < 8; w++) t += wsum[w];
            g_kstat[(bb * KK + k) * 2]     = m;
            g_kstat[(bb * KK + k) * 2 + 1] = 1.f / t;
        }
    }
}

// ---------------- BN stats phase 2: fold to per-channel affine ----------------
__global__ void bn_final(const float* __restrict__ gq, const float* __restrict__ bq,
                         const float* __restrict__ gv, const float* __restrict__ bv) {
    const int ci = threadIdx.x;
    if (ci >= 192) return;
    float s = 0.f, s2 = 0.f;
#pragma unroll
    for (int bb = 0; bb < 8; bb++) {
        s  += g_bnp[(ci * 8 + bb) * 2];
        s2 += g_bnp[(ci * 8 + bb) * 2 + 1];
    }
    const float N = (float)(BB * TT_);
    float mean = s / N;
    float var = s2 / N - mean * mean;
    float g = ci < 64 ? gq[ci] : gv[ci - 64];
    float be = ci < 64 ? bq[ci] : bv[ci - 64];
    float sc = g * rsqrtf(var + 1e-5f);
    g_scale[ci] = sc;
    g_shift[ci] = be - mean * sc;
}

// ---------------- lambda_c partials (softmax applied inline) ----------------
__global__ __launch_bounds__(256) void lamc_part() {
    const int b = blockIdx.y, chunk = blockIdx.x;
    const int t0 = chunk * 128;
    const float* pk = g_proj + ((size_t)b * NCH + 64) * TT_ + t0;
    const float* pv = g_proj + ((size_t)b * NCH + 80) * TT_ + t0;
    __shared__ float sk[KK][33];
    __shared__ float svt[32][132];
    __shared__ float skm[KK], ski[KK];
    const int tid = threadIdx.x;
    const int k = tid & 15, vg = tid >> 4;
    if (tid < KK) {
        skm[tid] = g_kstat[(b * KK + tid) * 2];
        ski[tid] = g_kstat[(b * KK + tid) * 2 + 1];
    }
    __syncthreads();
    float acc[8];
#pragma unroll
    for (int j = 0; j < 8; j++) acc[j] = 0.f;

#pragma unroll 1
    for (int sub = 0; sub < 4; sub++) {
        for (int i = tid; i < KK * 32; i += 256) {
            int kk = i >> 5, tt = i & 31;
            float raw = pk[(size_t)kk * TT_ + sub * 32 + tt];
            sk[kk][tt] = expf(raw - skm[kk]) * ski[kk];
        }
        for (int i = tid; i < NV * 32; i += 256) {
            int v = i >> 5, tt = i & 31;
            svt[tt][v] = pv[(size_t)v * TT_ + sub * 32 + tt];
        }
        __syncthreads();
#pragma unroll
        for (int t = 0; t < 32; t++) {
            const float a = sk[k][t];
            const float4 v0 = *(const float4*)&svt[t][vg * 8];
            const float4 v1 = *(const float4*)&svt[t][vg * 8 + 4];
            acc[0] += a * v0.x; acc[1] += a * v0.y; acc[2] += a * v0.z; acc[3] += a * v0.w;
            acc[4] += a * v1.x; acc[5] += a * v1.y; acc[6] += a * v1.z; acc[7] += a * v1.w;
        }
        __syncthreads();
    }
    float* pp = g_part + (((size_t)b * 32 + chunk) * KK + k) * VV + vg * 8;
#pragma unroll
    for (int j = 0; j < 8; j++) pp[j] = acc[j];
}

// ---------------- reduce partials + fold v BN affine ----------------
__global__ void lamc_reduce() {
    const int i = blockIdx.x * 256 + threadIdx.x;
    if (i >= BB * KK * VV) return;
    const int v = i & 127;
    const int b = i >> 11;
    const float* p = g_part + (size_t)b * 32 * KK * VV + (i & 2047);
    float s = 0.f;
#pragma unroll 1
    for (int c = 0; c < 32; c++) s += p[(size_t)c * KK * VV];
    g_lambda[i] = g_scale[64 + v] * s + g_shift[64 + v];
}

// ---------------- fused output v2: one head per block (low-reg, 2 blocks/SM) ----------------
#define M_TT 128
#define M_HW 144

__global__ __launch_bounds__(256) void lambda_main(const float* __restrict__ pos_w,
                                                   const float* __restrict__ pos_b,
                                                   float* __restrict__ out) {
    extern __shared__ float sm[];
    float* sq  = sm;                    // [16][128]   this head's qhat
    float* sv  = sm + KK * M_TT;        // [128][144]  vhat + halo
    float* slc = sv + NV * M_HW;        // [16][128]
    float* spw = slc + KK * VV;         // [16*15]
    float* spb = spw + KK * RR;         // [16]

    const int b = blockIdx.y;
    const int h = blockIdx.x & 3;
    const int t0 = (blockIdx.x >> 2) * M_TT;
    const int tid = threadIdx.x;
    const float* pq = g_proj + (size_t)b * NCH * TT_;
    const float* pv = pq + (size_t)80 * TT_;

    for (int i = tid; i < KK * M_TT; i += 256) {
        int kl = i >> 7, t = i & 127;
        int ch = h * KK + kl;
        sq[i] = pq[(size_t)ch * TT_ + t0 + t] * g_scale[ch] + g_shift[ch];
    }
    for (int i = tid; i < NV * M_HW; i += 256) {
        int v = i / M_HW, tr = i % M_HW;
        float val = 0.f;
        if (tr < M_TT + RR - 1) {
            int tg = t0 - (RR / 2) + tr;
            if (tg >= 0 && tg < TT_)
                val = pv[(size_t)v * TT_ + tg] * g_scale[64 + v] + g_shift[64 + v];
        }
        sv[i] = val;
    }
    for (int i = tid; i < KK * VV; i += 256) slc[i] = g_lambda[(size_t)b * KK * VV + i];
    if (tid < KK * RR) spw[tid] = pos_w[tid];
    if (tid < KK) spb[tid] = pos_b[tid];
    __syncthreads();

    const int t = tid & 127;
    const int vg = tid >> 7;   // 0..1, each handles 64 v

    float q[KK];
#pragma unroll
    for (int k = 0; k < KK; k++) q[k] = sq[k * M_TT + t];

    float qw[RR];
    float qb = 0.f;
#pragma unroll
    for (int r = 0; r < RR; r++) qw[r] = 0.f;
#pragma unroll
    for (int k = 0; k < KK; k++) {
        qb += q[k] * spb[k];
        const float* w = spw + k * RR;
#pragma unroll
        for (int r = 0; r < RR; r++) qw[r] += q[k] * w[r];
    }

    float* ob = out + ((size_t)b * 512 + h * VV) * TT_ + t0 + t;
#pragma unroll 2
    for (int v = 0; v < 64; v++) {
        const int vv = vg * 64 + v;
        float a = qb;
#pragma unroll
        for (int k = 0; k < KK; k++) a += q[k] * slc[k * VV + vv];
        const float* vp = sv + vv * M_HW + t;
#pragma unroll
        for (int r = 0; r < RR; r++) a += qw[r] * vp[r];
        ob[(size_t)vv * TT_] = a;
    }
}

// ---------------- launch ----------------
extern "C" void kernel_launch(void* const* d_in, const int* in_sizes, int n_in,
                              void* d_out, int out_size) {
    const float* x  = (const float*)d_in[0];
    const float* Wq = (const float*)d_in[1];
    const float* Wk = (const float*)d_in[2];
    const float* Wv = (const float*)d_in[3];
    const float* gq = (const float*)d_in[4];
    const float* bq = (const float*)d_in[5];
    const float* gv = (const float*)d_in[6];
    const float* bv = (const float*)d_in[7];
    const float* pw = (const float*)d_in[8];
    const float* pb = (const float*)d_in[9];
    float* out = (float*)d_out;

    const size_t main_smem = (size_t)(KK * M_TT + NV * M_HW + KK * VV + KK * RR + KK) * sizeof(float);
    cudaFuncSetAttribute(lambda_main, cudaFuncAttributeMaxDynamicSharedMemorySize, (int)main_smem);
    cudaFuncSetAttribute(gemm_mma, cudaFuncAttributeMaxDynamicSharedMemorySize, GM_SMEM);

    // stats_part is the 4th launch (ncu capture slot)
    xsplit<<<dim3(TT_ / 64, CC / 64, BB), 256>>>(x);
    pack_w_split<<<(MPAD * CC + 255) / 256, 256>>>(Wq, Wk, Wv);
    gemm_mma<<<dim3(NT / 128, 2), 128, GM_SMEM>>>();
    stats_part<<<dim3(208, 8), 256>>>();
    bn_final<<<1, 192>>>(gq, bq, gv, bv);
    lamc_part<<<dim3(32, BB), 256>>>();
    lamc_reduce<<<(BB * KK * VV + 255) / 256, 256>>>();
    lambda_main<<<dim3(4 * (TT_ / M_TT), BB), 256, main_smem>>>(pw, pb, out);
}